// round 1
// baseline (speedup 1.0000x reference)
#include <cuda_runtime.h>

typedef unsigned long long ull;

#define S_LEN 2048
#define NH 16
#define DIM 64
#define BLK 128
#define NBLK 16          // S_LEN / BLK
#define ROWSTRIDE 3072   // 3 * NH * DIM floats between consecutive s rows
#define SSTR 132         // padded stride for S / O2t tiles (mult of 4 -> 16B aligned rows)

// ---------- packed fp32x2 primitives (2x FFMA throughput on sm_103a) ----------
__device__ __forceinline__ ull pack2(float lo, float hi) {
    ull r; asm("mov.b64 %0, {%1, %2};" : "=l"(r) : "f"(lo), "f"(hi)); return r;
}
__device__ __forceinline__ void unpack2(ull v, float& lo, float& hi) {
    asm("mov.b64 {%0, %1}, %2;" : "=f"(lo), "=f"(hi) : "l"(v));
}
__device__ __forceinline__ void fma2(ull& d, ull a, ull b) {
    asm("fma.rn.f32x2 %0, %1, %2, %0;" : "+l"(d) : "l"(a), "l"(b));
}
__device__ __forceinline__ ull add2(ull a, ull b) {
    ull r; asm("add.rn.f32x2 %0, %1, %2;" : "=l"(r) : "l"(a), "l"(b)); return r;
}

// ---------- cooperative tile loaders (256 threads) ----------
// Transposed: dst[d][m] for d in [0,64), m in [0,128). src row m at src + m*ROWSTRIDE.
__device__ __forceinline__ void load_tile_T(float* dst, const float* src, int tid) {
#pragma unroll
    for (int it = 0; it < 8; ++it) {
        int f  = tid + it * 256;        // 0..2047 float4s
        int m  = f & 127;               // fastest -> conflict-free smem stores
        int dq = (f >> 7) << 2;
        float4 v = *reinterpret_cast<const float4*>(src + (size_t)m * ROWSTRIDE + dq);
        dst[(dq + 0) * 128 + m] = v.x;
        dst[(dq + 1) * 128 + m] = v.y;
        dst[(dq + 2) * 128 + m] = v.z;
        dst[(dq + 3) * 128 + m] = v.w;
    }
}
// Row-major: dst[m][d], [128][64]
__device__ __forceinline__ void load_tile_R(float* dst, const float* src, int tid) {
#pragma unroll
    for (int it = 0; it < 8; ++it) {
        int f  = tid + it * 256;
        int m  = f >> 4;
        int dq = (f & 15) << 2;
        *reinterpret_cast<float4*>(dst + m * 64 + dq) =
            *reinterpret_cast<const float4*>(src + (size_t)m * ROWSTRIDE + dq);
    }
}

// ---------- 128x128 <- [64][*]^T x [64][128]^T  (C[m][n] += sum_d A[m][d]*B[n][d]) ----------
// A stored d-major with stride ASTR, B stored d-major stride 128.
// Accumulator: acc[r][c] packs rows (m0+2r, m0+2r+1) at column n0+c.
template <int ASTR, bool NEG>
__device__ __forceinline__ void mma_TT(const float* aT, const float* bT,
                                       int m0, int n0, ull (&acc)[4][8]) {
#pragma unroll 4
    for (int d = 0; d < DIM; ++d) {
        const float* ar = aT + d * ASTR + m0;
        const float* br = bT + d * 128 + n0;
        ulonglong2 pa = *reinterpret_cast<const ulonglong2*>(ar);
        ulonglong2 pb = *reinterpret_cast<const ulonglong2*>(ar + 4);
        float4 k0 = *reinterpret_cast<const float4*>(br);
        float4 k1 = *reinterpret_cast<const float4*>(br + 4);
        float b0 = k0.x, b1 = k0.y, b2 = k0.z, b3 = k0.w;
        float b4 = k1.x, b5 = k1.y, b6 = k1.z, b7 = k1.w;
        if (NEG) { b0 = -b0; b1 = -b1; b2 = -b2; b3 = -b3;
                   b4 = -b4; b5 = -b5; b6 = -b6; b7 = -b7; }
        ull bb[8] = { pack2(b0,b0), pack2(b1,b1), pack2(b2,b2), pack2(b3,b3),
                      pack2(b4,b4), pack2(b5,b5), pack2(b6,b6), pack2(b7,b7) };
        ull a2[4] = { pa.x, pa.y, pb.x, pb.y };
#pragma unroll
        for (int r = 0; r < 4; ++r) {
#pragma unroll
            for (int c = 0; c < 8; ++c) fma2(acc[r][c], a2[r], bb[c]);
        }
    }
}

// ---------- 128x64 <- S[128][128] x B[128][64]  (C[m][c] += sum_s S[m][s]*B[s][c]) ----------
// S row-major stride SSTR; B row-major [128][64].
// Accumulator: acc[r][cp] packs columns (c0+2cp, c0+2cp+1) at row m0+r.
__device__ __forceinline__ void mma_SB(const float* sS_, const float* sB,
                                       int m0, int c0, ull (&acc)[8][2]) {
#pragma unroll 2
    for (int s = 0; s < 128; s += 4) {
        float4 av[8];
#pragma unroll
        for (int r = 0; r < 8; ++r)
            av[r] = *reinterpret_cast<const float4*>(sS_ + (m0 + r) * SSTR + s);
#pragma unroll
        for (int ss = 0; ss < 4; ++ss) {
            ulonglong2 bv = *reinterpret_cast<const ulonglong2*>(sB + (s + ss) * 64 + c0);
#pragma unroll
            for (int r = 0; r < 8; ++r) {
                float a = (&av[r].x)[ss];
                ull aa = pack2(a, a);
                fma2(acc[r][0], aa, bv.x);
                fma2(acc[r][1], aa, bv.y);
            }
        }
    }
}

// ---------- store masked score tile to smem (row-major, stride SSTR) ----------
__device__ __forceinline__ void store_S(float* sS_, ull (&acc)[4][8],
                                        int m0, int n0, bool diag) {
#pragma unroll
    for (int r = 0; r < 4; ++r) {
        float lo[8], hi[8];
#pragma unroll
        for (int c = 0; c < 8; ++c) unpack2(acc[r][c], lo[c], hi[c]);
        int row0 = m0 + 2 * r;
        if (diag) {
#pragma unroll
            for (int c = 0; c < 8; ++c) {
                if (row0     < n0 + c) lo[c] = 0.0f;
                if (row0 + 1 < n0 + c) hi[c] = 0.0f;
            }
        }
        float* p0 = sS_ + row0 * SSTR + n0;
        float* p1 = p0 + SSTR;
        *reinterpret_cast<float4*>(p0)     = make_float4(lo[0], lo[1], lo[2], lo[3]);
        *reinterpret_cast<float4*>(p0 + 4) = make_float4(lo[4], lo[5], lo[6], lo[7]);
        *reinterpret_cast<float4*>(p1)     = make_float4(hi[0], hi[1], hi[2], hi[3]);
        *reinterpret_cast<float4*>(p1 + 4) = make_float4(hi[4], hi[5], hi[6], hi[7]);
    }
}

// smem: sQt[64*128] sKt[64*128] sKV[128*64] sS[128*SSTR] sO2[64*SSTR]
#define SMEM_FLOATS (64*128 + 64*128 + 128*64 + 128*SSTR + 64*SSTR)

__global__ void __launch_bounds__(256, 1)
ttt_kernel(const float* __restrict__ qkv, float* __restrict__ out) {
    extern __shared__ float sm[];
    float* sQt = sm;                       // [64][128]  Q^T (d-major)
    float* sKt = sQt + 64 * 128;           // [64][128]  K^T (d-major)
    float* sKV = sKt + 64 * 128;           // [128][64]  K (pass1) / V (pass2) row-major
    float* sS  = sKV + 128 * 64;           // [128][SSTR] score tile, row-major
    float* sO2 = sS + 128 * SSTR;          // [64][SSTR]  O2^T (d-major)

    const int tid = threadIdx.x;
    const int tx = tid & 15, ty = tid >> 4;
    const int m0 = ty << 3, n0 = tx << 3, c0 = tx << 2;
    const int iBlk = (NBLK - 1) - (int)blockIdx.y;   // heavy T-blocks launch first
    const int bh = blockIdx.x;
    const int b = bh >> 4, h = bh & 15;

    const float* base = qkv + (size_t)b * S_LEN * ROWSTRIDE + h * DIM;
    const float* gQ = base;                 // comp 0
    const float* gK = base + NH * DIM;      // comp 1
    const float* gV = base + 2 * NH * DIM;  // comp 2
    const int t0 = iBlk * BLK;

    load_tile_T(sQt, gQ + (size_t)t0 * ROWSTRIDE, tid);

    // ---------------- pass 1: O2 = tril(QK^T) K ----------------
    ull o2acc[8][2];
#pragma unroll
    for (int r = 0; r < 8; ++r) { o2acc[r][0] = 0ull; o2acc[r][1] = 0ull; }

    for (int j = 0; j <= iBlk; ++j) {
        __syncthreads();
        const float* kblk = gK + (size_t)j * BLK * ROWSTRIDE;
        load_tile_T(sKt, kblk, tid);
        load_tile_R(sKV, kblk, tid);
        __syncthreads();

        ull acc[4][8];
#pragma unroll
        for (int r = 0; r < 4; ++r) {
#pragma unroll
            for (int c = 0; c < 8; ++c) acc[r][c] = 0ull;
        }
        mma_TT<128, false>(sQt, sKt, m0, n0, acc);       // A1 tile
        store_S(sS, acc, m0, n0, j == iBlk);             // masked A1 -> smem
        __syncthreads();
        mma_SB(sS, sKV, m0, c0, o2acc);                  // O2 += A1 * K
    }

    __syncthreads();
    // stash O2 transposed (d-major) for pass-2 O2*K^T
#pragma unroll
    for (int r = 0; r < 8; ++r) {
#pragma unroll
        for (int cp = 0; cp < 2; ++cp) {
            float lo, hi; unpack2(o2acc[r][cp], lo, hi);
            sO2[(c0 + 2 * cp    ) * SSTR + m0 + r] = lo;
            sO2[(c0 + 2 * cp + 1) * SSTR + m0 + r] = hi;
        }
    }
    __syncthreads();

    // ---------------- pass 2: out = (2*A1 - tril(O2 K^T)) V ----------------
    ull outacc[8][2];
#pragma unroll
    for (int r = 0; r < 8; ++r) { outacc[r][0] = 0ull; outacc[r][1] = 0ull; }

    for (int j = 0; j <= iBlk; ++j) {
        __syncthreads();
        const float* kblk = gK + (size_t)j * BLK * ROWSTRIDE;
        const float* vblk = gV + (size_t)j * BLK * ROWSTRIDE;
        load_tile_T(sKt, kblk, tid);
        load_tile_R(sKV, vblk, tid);
        __syncthreads();

        ull acc[4][8];
#pragma unroll
        for (int r = 0; r < 4; ++r) {
#pragma unroll
            for (int c = 0; c < 8; ++c) acc[r][c] = 0ull;
        }
        mma_TT<128, false>(sQt, sKt, m0, n0, acc);       // A1 tile (recompute)
#pragma unroll
        for (int r = 0; r < 4; ++r) {
#pragma unroll
            for (int c = 0; c < 8; ++c) acc[r][c] = add2(acc[r][c], acc[r][c]);  // 2*A1
        }
        mma_TT<SSTR, true>(sO2, sKt, m0, n0, acc);       // -= O2 * K^T
        store_S(sS, acc, m0, n0, j == iBlk);             // masked (2A1 - A2)
        __syncthreads();
        mma_SB(sS, sKV, m0, c0, outacc);                 // out += A * V
    }

    // final store: out[b][t][h][d]
#pragma unroll
    for (int r = 0; r < 8; ++r) {
        float x, y, z, w;
        unpack2(outacc[r][0], x, y);
        unpack2(outacc[r][1], z, w);
        size_t off = (((size_t)b * S_LEN + t0 + m0 + r) * NH + h) * DIM + c0;
        *reinterpret_cast<float4*>(out + off) = make_float4(x, y, z, w);
    }
}

extern "C" void kernel_launch(void* const* d_in, const int* in_sizes, int n_in,
                              void* d_out, int out_size) {
    const float* qkv = (const float*)d_in[0];
    float* out = (float*)d_out;
    const int smem_bytes = SMEM_FLOATS * (int)sizeof(float);   // 199,680 B
    cudaFuncSetAttribute(ttt_kernel, cudaFuncAttributeMaxDynamicSharedMemorySize, smem_bytes);
    dim3 grid(32 /*b*h*/, NBLK /*reversed T-blocks*/);
    ttt_kernel<<<grid, 256, smem_bytes>>>(qkv, out);
}

// round 3
// speedup vs baseline: 2.5062x; 2.5062x over previous
#include <cuda_runtime.h>
#include <cuda_bf16.h>
#include <cstdint>

typedef uint32_t u32;

#define S_LEN 2048
#define NH 16
#define DIM 64
#define BLK 128
#define NBLK 16
#define ROWSTRIDE 3072   // 3*NH*DIM floats between consecutive s rows

// half-tile (one of hi/lo) sizes in bytes
#define HL64  16384      // [128][64] bf16
#define HL128 32768      // [128][128] bf16
// smem byte offsets (each buffer = hi tile then lo tile)
#define OFF_Q   0
#define OFF_K   (OFF_Q + 2*HL64)
#define OFF_V   (OFF_K + 2*HL64)
#define OFF_S   (OFF_V + 2*HL64)
#define OFF_O2  (OFF_S + 2*HL128)
#define SMEM_TOTAL (OFF_O2 + 2*HL64)   // 196608 B

// ------------------------------------------------------------------ helpers
__device__ __forceinline__ u32 smem_u32(const void* p) {
    u32 a; asm("{ .reg .u64 t; cvta.to.shared.u64 t, %1; cvt.u32.u64 %0, t; }"
               : "=r"(a) : "l"(p));
    return a;
}
// XOR-swizzled byte offsets: 128B rows (64 bf16) and 256B rows (128 bf16)
__device__ __forceinline__ u32 off64(int r, int cb)  { return (u32)(r * 128 + (cb ^ ((r & 7) << 4))); }
__device__ __forceinline__ u32 off128(int r, int cb) { return (u32)(r * 256 + (cb ^ ((r & 7) << 4))); }

__device__ __forceinline__ void ldsm4(u32 a, u32& r0, u32& r1, u32& r2, u32& r3) {
    asm volatile("ldmatrix.sync.aligned.m8n8.x4.shared.b16 {%0,%1,%2,%3}, [%4];"
        : "=r"(r0), "=r"(r1), "=r"(r2), "=r"(r3) : "r"(a));
}
__device__ __forceinline__ void ldsm4t(u32 a, u32& r0, u32& r1, u32& r2, u32& r3) {
    asm volatile("ldmatrix.sync.aligned.m8n8.x4.trans.shared.b16 {%0,%1,%2,%3}, [%4];"
        : "=r"(r0), "=r"(r1), "=r"(r2), "=r"(r3) : "r"(a));
}
__device__ __forceinline__ void mma_bf16(float* c, u32 a0, u32 a1, u32 a2, u32 a3,
                                         u32 b0, u32 b1) {
    asm volatile("mma.sync.aligned.m16n8k16.row.col.f32.bf16.bf16.f32 "
        "{%0,%1,%2,%3}, {%4,%5,%6,%7}, {%8,%9}, {%0,%1,%2,%3};"
        : "+f"(c[0]), "+f"(c[1]), "+f"(c[2]), "+f"(c[3])
        : "r"(a0), "r"(a1), "r"(a2), "r"(a3), "r"(b0), "r"(b1));
}
__device__ __forceinline__ void split2(float x, __nv_bfloat16& h, __nv_bfloat16& l) {
    h = __float2bfloat16(x);
    l = __float2bfloat16(x - __bfloat162float(h));
}

// ---- load 128x64 fp32 gmem block -> split-bf16 hi/lo swizzled smem tiles ----
__device__ __forceinline__ void load_split(char* sm, int base, const float* src,
                                           float scale, int tid) {
#pragma unroll
    for (int it = 0; it < 8; ++it) {
        int f = tid + it * 256;
        int s = f >> 4, dq = (f & 15) << 2;
        float4 v = *reinterpret_cast<const float4*>(src + (size_t)s * ROWSTRIDE + dq);
        __nv_bfloat16 h0, l0, h1, l1, h2, l2, h3, l3;
        split2(v.x * scale, h0, l0); split2(v.y * scale, h1, l1);
        split2(v.z * scale, h2, l2); split2(v.w * scale, h3, l3);
        u32 o = off64(s, dq << 1);
        __nv_bfloat162 p;
        p.x = h0; p.y = h1; *reinterpret_cast<__nv_bfloat162*>(sm + base + o)            = p;
        p.x = h2; p.y = h3; *reinterpret_cast<__nv_bfloat162*>(sm + base + o + 4)        = p;
        p.x = l0; p.y = l1; *reinterpret_cast<__nv_bfloat162*>(sm + base + HL64 + o)     = p;
        p.x = l2; p.y = l3; *reinterpret_cast<__nv_bfloat162*>(sm + base + HL64 + o + 4) = p;
    }
}

// ---- GEMM: acc[128x128 slice] += A[128x64] * (Ktile[128x64])^T, 3-term split ----
// A rows mbase..mbase+31 (this warp), B rows nbase..nbase+63. Both off64 layout.
__device__ __forceinline__ void gemm_nT(u32 aHi, u32 bHi, float (&acc)[2][8][4],
                                        int lane, int mbase, int nbase) {
    const int arL = lane & 15, acL = (lane >> 4) << 4;
    const int brL = ((lane >> 4) << 3) + (lane & 7), bcL = ((lane >> 3) & 1) << 4;
#pragma unroll
    for (int kk = 0; kk < 4; ++kk) {
        const int kb = kk << 5;
        u32 aH[2][4], aL[2][4];
#pragma unroll
        for (int mt = 0; mt < 2; ++mt) {
            u32 ad = aHi + off64(mbase + mt * 16 + arL, kb + acL);
            ldsm4(ad,        aH[mt][0], aH[mt][1], aH[mt][2], aH[mt][3]);
            ldsm4(ad + HL64, aL[mt][0], aL[mt][1], aL[mt][2], aL[mt][3]);
        }
#pragma unroll
        for (int nt2 = 0; nt2 < 4; ++nt2) {
            u32 bd = bHi + off64(nbase + nt2 * 16 + brL, kb + bcL);
            u32 bh0, bh1, bh2, bh3, bl0, bl1, bl2, bl3;
            ldsm4(bd,        bh0, bh1, bh2, bh3);
            ldsm4(bd + HL64, bl0, bl1, bl2, bl3);
#pragma unroll
            for (int mt = 0; mt < 2; ++mt) {
                float* c0 = acc[mt][nt2 * 2];
                float* c1 = acc[mt][nt2 * 2 + 1];
                mma_bf16(c0, aH[mt][0], aH[mt][1], aH[mt][2], aH[mt][3], bh0, bh1);
                mma_bf16(c0, aH[mt][0], aH[mt][1], aH[mt][2], aH[mt][3], bl0, bl1);
                mma_bf16(c0, aL[mt][0], aL[mt][1], aL[mt][2], aL[mt][3], bh0, bh1);
                mma_bf16(c1, aH[mt][0], aH[mt][1], aH[mt][2], aH[mt][3], bh2, bh3);
                mma_bf16(c1, aH[mt][0], aH[mt][1], aH[mt][2], aH[mt][3], bl2, bl3);
                mma_bf16(c1, aL[mt][0], aL[mt][1], aL[mt][2], aL[mt][3], bh2, bh3);
            }
        }
    }
}

// ---- GEMM: acc[128x64 slice] += S[128x128] * Btile[128x64], 3-term split ----
// S off128 layout; B fragments via ldmatrix.trans (B^T[d][s] from [s][d] tile).
__device__ __forceinline__ void gemm_sB(u32 sHi, u32 bHi, float (&acc)[2][4][4],
                                        int lane, int mbase, int cbase) {
    const int arL = lane & 15, acL = (lane >> 4) << 4;
    const int brL = (((lane >> 3) & 1) << 3) + (lane & 7), bcL = (lane >> 4) << 4;
#pragma unroll
    for (int kk = 0; kk < 8; ++kk) {
        const int kb = kk << 5;   // byte offset along s within S row
        const int s0 = kk << 4;   // s-row base in B tile
        u32 aH[2][4], aL[2][4];
#pragma unroll
        for (int mt = 0; mt < 2; ++mt) {
            u32 ad = sHi + off128(mbase + mt * 16 + arL, kb + acL);
            ldsm4(ad,         aH[mt][0], aH[mt][1], aH[mt][2], aH[mt][3]);
            ldsm4(ad + HL128, aL[mt][0], aL[mt][1], aL[mt][2], aL[mt][3]);
        }
#pragma unroll
        for (int nt2 = 0; nt2 < 2; ++nt2) {
            u32 bd = bHi + off64(s0 + brL, ((cbase + nt2 * 16) << 1) + bcL);
            u32 bh0, bh1, bh2, bh3, bl0, bl1, bl2, bl3;
            ldsm4t(bd,        bh0, bh1, bh2, bh3);
            ldsm4t(bd + HL64, bl0, bl1, bl2, bl3);
#pragma unroll
            for (int mt = 0; mt < 2; ++mt) {
                float* c0 = acc[mt][nt2 * 2];
                float* c1 = acc[mt][nt2 * 2 + 1];
                mma_bf16(c0, aH[mt][0], aH[mt][1], aH[mt][2], aH[mt][3], bh0, bh1);
                mma_bf16(c0, aH[mt][0], aH[mt][1], aH[mt][2], aH[mt][3], bl0, bl1);
                mma_bf16(c0, aL[mt][0], aL[mt][1], aL[mt][2], aL[mt][3], bh0, bh1);
                mma_bf16(c1, aH[mt][0], aH[mt][1], aH[mt][2], aH[mt][3], bh2, bh3);
                mma_bf16(c1, aH[mt][0], aH[mt][1], aH[mt][2], aH[mt][3], bl2, bl3);
                mma_bf16(c1, aL[mt][0], aL[mt][1], aL[mt][2], aL[mt][3], bh2, bh3);
            }
        }
    }
}

// ---- masked split store of score tile -> sS (off128, hi/lo) ----
__device__ __forceinline__ void store_S(char* sm, float (&acc)[2][8][4],
                                        int lane, int mbase, int nbase, bool diag) {
#pragma unroll
    for (int mt = 0; mt < 2; ++mt) {
#pragma unroll
        for (int nt = 0; nt < 8; ++nt) {
            int col = nbase + nt * 8 + (lane & 3) * 2;
#pragma unroll
            for (int rr = 0; rr < 2; ++rr) {
                int row = mbase + mt * 16 + (lane >> 2) + rr * 8;
                float v0 = acc[mt][nt][rr * 2 + 0];
                float v1 = acc[mt][nt][rr * 2 + 1];
                if (diag) {
                    if (col     > row) v0 = 0.0f;
                    if (col + 1 > row) v1 = 0.0f;
                }
                __nv_bfloat16 h0, l0, h1, l1;
                split2(v0, h0, l0); split2(v1, h1, l1);
                u32 o = off128(row, col << 1);
                __nv_bfloat162 p;
                p.x = h0; p.y = h1; *reinterpret_cast<__nv_bfloat162*>(sm + OFF_S + o)         = p;
                p.x = l0; p.y = l1; *reinterpret_cast<__nv_bfloat162*>(sm + OFF_S + HL128 + o) = p;
            }
        }
    }
}

__global__ void __launch_bounds__(256, 1)
ttt_mma_kernel(const float* __restrict__ qkv, float* __restrict__ out) {
    extern __shared__ char sm[];
    const u32 sb = smem_u32(sm);
    const int tid = threadIdx.x, lane = tid & 31, wid = tid >> 5;
    const int wm = wid & 3, wn = wid >> 2;
    const int mbase = wm * 32;

    const int iBlk = (NBLK - 1) - (int)blockIdx.y;   // heavy T-blocks first
    const int bh = blockIdx.x, b = bh >> 4, h = bh & 15;
    const float* base = qkv + (size_t)b * S_LEN * ROWSTRIDE + h * DIM;
    const float* gQ = base;
    const float* gK = base + NH * DIM;
    const float* gV = base + 2 * NH * DIM;
    const int t0 = iBlk * BLK;

    load_split(sm, OFF_Q, gQ + (size_t)t0 * ROWSTRIDE, 2.0f, tid);   // 2Q

    // ================= pass 1: O2acc = tril(2Q K^T) K  (= 2*O2) =================
    float o2acc[2][4][4];
#pragma unroll
    for (int mt = 0; mt < 2; ++mt)
#pragma unroll
        for (int nt = 0; nt < 4; ++nt)
#pragma unroll
            for (int e = 0; e < 4; ++e) o2acc[mt][nt][e] = 0.0f;

    for (int j = 0; j <= iBlk; ++j) {
        __syncthreads();   // previous gemm_sB done with sK
        load_split(sm, OFF_K, gK + (size_t)j * BLK * ROWSTRIDE, 1.0f, tid);
        __syncthreads();

        float acc1[2][8][4];
#pragma unroll
        for (int mt = 0; mt < 2; ++mt)
#pragma unroll
            for (int nt = 0; nt < 8; ++nt)
#pragma unroll
                for (int e = 0; e < 4; ++e) acc1[mt][nt][e] = 0.0f;

        gemm_nT(sb + OFF_Q, sb + OFF_K, acc1, lane, mbase, wn * 64);   // 2Q K^T
        store_S(sm, acc1, lane, mbase, wn * 64, j == iBlk);            // tril -> sS
        __syncthreads();
        gemm_sB(sb + OFF_S, sb + OFF_K, o2acc, lane, mbase, wn * 32);  // += S K
    }

    // stash -O2 = -0.5 * o2acc into sO2 (hi/lo, off64)
#pragma unroll
    for (int mt = 0; mt < 2; ++mt) {
#pragma unroll
        for (int nt = 0; nt < 4; ++nt) {
            int col = wn * 32 + nt * 8 + (lane & 3) * 2;
#pragma unroll
            for (int rr = 0; rr < 2; ++rr) {
                int row = mbase + mt * 16 + (lane >> 2) + rr * 8;
                float v0 = -0.5f * o2acc[mt][nt][rr * 2 + 0];
                float v1 = -0.5f * o2acc[mt][nt][rr * 2 + 1];
                __nv_bfloat16 h0, l0, h1, l1;
                split2(v0, h0, l0); split2(v1, h1, l1);
                u32 o = off64(row, col << 1);
                __nv_bfloat162 p;
                p.x = h0; p.y = h1; *reinterpret_cast<__nv_bfloat162*>(sm + OFF_O2 + o)        = p;
                p.x = l0; p.y = l1; *reinterpret_cast<__nv_bfloat162*>(sm + OFF_O2 + HL64 + o) = p;
            }
        }
    }

    // ========== pass 2: out = tril(2Q K^T + (-O2) K^T) V = (2A1 - A2) V ==========
    float outacc[2][4][4];
#pragma unroll
    for (int mt = 0; mt < 2; ++mt)
#pragma unroll
        for (int nt = 0; nt < 4; ++nt)
#pragma unroll
            for (int e = 0; e < 4; ++e) outacc[mt][nt][e] = 0.0f;

    for (int j = 0; j <= iBlk; ++j) {
        __syncthreads();   // prev gemm_sB done with sV; also fences sO2 stores (j=0)
        load_split(sm, OFF_K, gK + (size_t)j * BLK * ROWSTRIDE, 1.0f, tid);
        load_split(sm, OFF_V, gV + (size_t)j * BLK * ROWSTRIDE, 1.0f, tid);
        __syncthreads();

        float acc1[2][8][4];
#pragma unroll
        for (int mt = 0; mt < 2; ++mt)
#pragma unroll
            for (int nt = 0; nt < 8; ++nt)
#pragma unroll
                for (int e = 0; e < 4; ++e) acc1[mt][nt][e] = 0.0f;

        gemm_nT(sb + OFF_Q,  sb + OFF_K, acc1, lane, mbase, wn * 64);  // 2Q K^T
        gemm_nT(sb + OFF_O2, sb + OFF_K, acc1, lane, mbase, wn * 64);  // += (-O2) K^T
        store_S(sm, acc1, lane, mbase, wn * 64, j == iBlk);            // tril -> sS
        __syncthreads();
        gemm_sB(sb + OFF_S, sb + OFF_V, outacc, lane, mbase, wn * 32); // += S V
    }

    // final store: out[b][t][h][d]
#pragma unroll
    for (int mt = 0; mt < 2; ++mt) {
#pragma unroll
        for (int nt = 0; nt < 4; ++nt) {
            int col = wn * 32 + nt * 8 + (lane & 3) * 2;
#pragma unroll
            for (int rr = 0; rr < 2; ++rr) {
                int row = mbase + mt * 16 + (lane >> 2) + rr * 8;
                float2 v = make_float2(outacc[mt][nt][rr * 2 + 0],
                                       outacc[mt][nt][rr * 2 + 1]);
                size_t off = (((size_t)b * S_LEN + t0 + row) * NH + h) * DIM + col;
                *reinterpret_cast<float2*>(out + off) = v;
            }
        }
    }
}

extern "C" void kernel_launch(void* const* d_in, const int* in_sizes, int n_in,
                              void* d_out, int out_size) {
    const float* qkv = (const float*)d_in[0];
    float* out = (float*)d_out;
    cudaFuncSetAttribute(ttt_mma_kernel, cudaFuncAttributeMaxDynamicSharedMemorySize,
                         SMEM_TOTAL);
    dim3 grid(32 /*b*h*/, NBLK /*reversed T-blocks*/);
    ttt_mma_kernel<<<grid, 256, SMEM_TOTAL>>>(qkv, out);
}

// round 4
// speedup vs baseline: 2.5926x; 1.0344x over previous
#include <cuda_runtime.h>
#include <cuda_bf16.h>
#include <cstdint>

typedef uint32_t u32;

#define S_LEN 2048
#define NH 16
#define DIM 64
#define BLK 128
#define NBLK 16
#define ROWSTRIDE 3072   // 3*NH*DIM floats between consecutive s rows

#define HL64 16384       // one [128][64] bf16 half-tile (hi or lo)
// smem: each buffer = hi tile then lo tile (off64 swizzled layout)
#define OFF_Q   0
#define OFF_K   (OFF_Q + 2*HL64)
#define OFF_V   (OFF_K + 2*HL64)
#define OFF_O2  (OFF_V + 2*HL64)
#define SMEM_TOTAL (OFF_O2 + 2*HL64)   // 131072 B
#define STG_OFF OFF_K                   // f32 staging for cross-warp reductions (32KB)

// ------------------------------------------------------------------ helpers
__device__ __forceinline__ u32 smem_u32(const void* p) {
    u32 a; asm("{ .reg .u64 t; cvta.to.shared.u64 t, %1; cvt.u32.u64 %0, t; }"
               : "=r"(a) : "l"(p));
    return a;
}
__device__ __forceinline__ u32 off64(int r, int cb) { return (u32)(r * 128 + (cb ^ ((r & 7) << 4))); }

__device__ __forceinline__ void ldsm4(u32 a, u32& r0, u32& r1, u32& r2, u32& r3) {
    asm volatile("ldmatrix.sync.aligned.m8n8.x4.shared.b16 {%0,%1,%2,%3}, [%4];"
        : "=r"(r0), "=r"(r1), "=r"(r2), "=r"(r3) : "r"(a));
}
__device__ __forceinline__ void ldsm4t(u32 a, u32& r0, u32& r1, u32& r2, u32& r3) {
    asm volatile("ldmatrix.sync.aligned.m8n8.x4.trans.shared.b16 {%0,%1,%2,%3}, [%4];"
        : "=r"(r0), "=r"(r1), "=r"(r2), "=r"(r3) : "r"(a));
}
__device__ __forceinline__ void mma_bf16(float* c, u32 a0, u32 a1, u32 a2, u32 a3,
                                         u32 b0, u32 b1) {
    asm volatile("mma.sync.aligned.m16n8k16.row.col.f32.bf16.bf16.f32 "
        "{%0,%1,%2,%3}, {%4,%5,%6,%7}, {%8,%9}, {%0,%1,%2,%3};"
        : "+f"(c[0]), "+f"(c[1]), "+f"(c[2]), "+f"(c[3])
        : "r"(a0), "r"(a1), "r"(a2), "r"(a3), "r"(b0), "r"(b1));
}
__device__ __forceinline__ void split2(float x, __nv_bfloat16& h, __nv_bfloat16& l) {
    h = __float2bfloat16(x);
    l = __float2bfloat16(x - __bfloat162float(h));
}
// split two floats -> packed bf16x2 hi reg + lo reg (A-fragment layout)
__device__ __forceinline__ void split_pack(float v0, float v1, u32& hp, u32& lp) {
    __nv_bfloat16 h0, l0, h1, l1;
    split2(v0, h0, l0); split2(v1, h1, l1);
    __nv_bfloat162 hh; hh.x = h0; hh.y = h1;
    __nv_bfloat162 ll; ll.x = l0; ll.y = l1;
    hp = *reinterpret_cast<u32*>(&hh);
    lp = *reinterpret_cast<u32*>(&ll);
}

// ---- LDG phase: 128x64 fp32 tile -> 8 float4 regs per thread (256 thr) ----
__device__ __forceinline__ void ldg_tile(float4 (&v)[8], const float* src, int tid) {
#pragma unroll
    for (int it = 0; it < 8; ++it) {
        int f = tid + it * 256;
        int s = f >> 4, dq = (f & 15) << 2;
        v[it] = *reinterpret_cast<const float4*>(src + (size_t)s * ROWSTRIDE + dq);
    }
}
// ---- STS phase: regs -> split-bf16 hi/lo swizzled smem tiles ----
__device__ __forceinline__ void sts_split(char* sm, int base, const float4 (&v)[8],
                                          float scale, int tid) {
#pragma unroll
    for (int it = 0; it < 8; ++it) {
        int f = tid + it * 256;
        int s = f >> 4, dq = (f & 15) << 2;
        __nv_bfloat16 h0, l0, h1, l1, h2, l2, h3, l3;
        split2(v[it].x * scale, h0, l0); split2(v[it].y * scale, h1, l1);
        split2(v[it].z * scale, h2, l2); split2(v[it].w * scale, h3, l3);
        u32 o = off64(s, dq << 1);
        __nv_bfloat162 p;
        p.x = h0; p.y = h1; *reinterpret_cast<__nv_bfloat162*>(sm + base + o)            = p;
        p.x = h2; p.y = h3; *reinterpret_cast<__nv_bfloat162*>(sm + base + o + 4)        = p;
        p.x = l0; p.y = l1; *reinterpret_cast<__nv_bfloat162*>(sm + base + HL64 + o)     = p;
        p.x = l2; p.y = l3; *reinterpret_cast<__nv_bfloat162*>(sm + base + HL64 + o + 4) = p;
    }
}

// ---- GEMM1: acc[32x64 slice] += A[128x64] * (B[128x64])^T, 3-term split ----
__device__ __forceinline__ void gemm_nT(u32 aHi, u32 bHi, float (&acc)[2][8][4],
                                        int lane, int mbase, int nbase) {
    const int arL = lane & 15, acL = (lane >> 4) << 4;
    const int brL = ((lane >> 4) << 3) + (lane & 7), bcL = ((lane >> 3) & 1) << 4;
#pragma unroll
    for (int kk = 0; kk < 4; ++kk) {
        const int kb = kk << 5;
        u32 aH[2][4], aL[2][4];
#pragma unroll
        for (int mt = 0; mt < 2; ++mt) {
            u32 ad = aHi + off64(mbase + mt * 16 + arL, kb + acL);
            ldsm4(ad,        aH[mt][0], aH[mt][1], aH[mt][2], aH[mt][3]);
            ldsm4(ad + HL64, aL[mt][0], aL[mt][1], aL[mt][2], aL[mt][3]);
        }
#pragma unroll
        for (int nt2 = 0; nt2 < 4; ++nt2) {
            u32 bd = bHi + off64(nbase + nt2 * 16 + brL, kb + bcL);
            u32 bh0, bh1, bh2, bh3, bl0, bl1, bl2, bl3;
            ldsm4(bd,        bh0, bh1, bh2, bh3);
            ldsm4(bd + HL64, bl0, bl1, bl2, bl3);
#pragma unroll
            for (int mt = 0; mt < 2; ++mt) {
                float* c0 = acc[mt][nt2 * 2];
                float* c1 = acc[mt][nt2 * 2 + 1];
                mma_bf16(c0, aH[mt][0], aH[mt][1], aH[mt][2], aH[mt][3], bh0, bh1);
                mma_bf16(c0, aH[mt][0], aH[mt][1], aH[mt][2], aH[mt][3], bl0, bl1);
                mma_bf16(c0, aL[mt][0], aL[mt][1], aL[mt][2], aL[mt][3], bh0, bh1);
                mma_bf16(c1, aH[mt][0], aH[mt][1], aH[mt][2], aH[mt][3], bh2, bh3);
                mma_bf16(c1, aH[mt][0], aH[mt][1], aH[mt][2], aH[mt][3], bl2, bl3);
                mma_bf16(c1, aL[mt][0], aL[mt][1], aL[mt][2], aL[mt][3], bh2, bh3);
            }
        }
    }
}

// ---- mask + in-register split of score slice into A-operand packs ----
__device__ __forceinline__ void mask_pack(float (&acc)[2][8][4],
                                          u32 (&pH)[2][4][4], u32 (&pL)[2][4][4],
                                          int lane, int mbase, int nbase, bool diag) {
    if (diag) {
#pragma unroll
        for (int mt = 0; mt < 2; ++mt)
#pragma unroll
            for (int nt = 0; nt < 8; ++nt) {
                int col = nbase + nt * 8 + ((lane & 3) << 1);
#pragma unroll
                for (int rr = 0; rr < 2; ++rr) {
                    int row = mbase + mt * 16 + (lane >> 2) + rr * 8;
                    if (col     > row) acc[mt][nt][rr * 2 + 0] = 0.0f;
                    if (col + 1 > row) acc[mt][nt][rr * 2 + 1] = 0.0f;
                }
            }
    }
#pragma unroll
    for (int mt = 0; mt < 2; ++mt)
#pragma unroll
        for (int kk = 0; kk < 4; ++kk) {
            split_pack(acc[mt][2*kk  ][0], acc[mt][2*kk  ][1], pH[mt][kk][0], pL[mt][kk][0]);
            split_pack(acc[mt][2*kk  ][2], acc[mt][2*kk  ][3], pH[mt][kk][1], pL[mt][kk][1]);
            split_pack(acc[mt][2*kk+1][0], acc[mt][2*kk+1][1], pH[mt][kk][2], pL[mt][kk][2]);
            split_pack(acc[mt][2*kk+1][2], acc[mt][2*kk+1][3], pH[mt][kk][3], pL[mt][kk][3]);
        }
}

// ---- GEMM2: po[32x64] += S_slice(regs) * B[krange x 64], B via ldmatrix.trans ----
__device__ __forceinline__ void gemm2_reg(const u32 (&pH)[2][4][4], const u32 (&pL)[2][4][4],
                                          u32 bHi, float (&po)[2][8][4],
                                          int lane, int kbase) {
    const int brL = (((lane >> 3) & 1) << 3) + (lane & 7), bcL = (lane >> 4) << 4;
#pragma unroll
    for (int kk = 0; kk < 4; ++kk) {
#pragma unroll
        for (int nt2 = 0; nt2 < 4; ++nt2) {
            u32 bd = bHi + off64(kbase + kk * 16 + brL, (nt2 << 5) + bcL);
            u32 bh0, bh1, bh2, bh3, bl0, bl1, bl2, bl3;
            ldsm4t(bd,        bh0, bh1, bh2, bh3);
            ldsm4t(bd + HL64, bl0, bl1, bl2, bl3);
#pragma unroll
            for (int mt = 0; mt < 2; ++mt) {
                float* c0 = po[mt][nt2 * 2];
                float* c1 = po[mt][nt2 * 2 + 1];
                mma_bf16(c0, pH[mt][kk][0], pH[mt][kk][1], pH[mt][kk][2], pH[mt][kk][3], bh0, bh1);
                mma_bf16(c0, pH[mt][kk][0], pH[mt][kk][1], pH[mt][kk][2], pH[mt][kk][3], bl0, bl1);
                mma_bf16(c0, pL[mt][kk][0], pL[mt][kk][1], pL[mt][kk][2], pL[mt][kk][3], bh0, bh1);
                mma_bf16(c1, pH[mt][kk][0], pH[mt][kk][1], pH[mt][kk][2], pH[mt][kk][3], bh2, bh3);
                mma_bf16(c1, pH[mt][kk][0], pH[mt][kk][1], pH[mt][kk][2], pH[mt][kk][3], bl2, bl3);
                mma_bf16(c1, pL[mt][kk][0], pL[mt][kk][1], pL[mt][kk][2], pL[mt][kk][3], bh2, bh3);
            }
        }
    }
}

#define ZERO_PO(po) \
    _Pragma("unroll") for (int mt = 0; mt < 2; ++mt) \
    _Pragma("unroll") for (int nt = 0; nt < 8; ++nt) \
    _Pragma("unroll") for (int e = 0; e < 4; ++e) (po)[mt][nt][e] = 0.0f;

__global__ void __launch_bounds__(256, 1)
ttt_mma_kernel(const float* __restrict__ qkv, float* __restrict__ out) {
    extern __shared__ char sm[];
    const u32 sb = smem_u32(sm);
    const int tid = threadIdx.x, lane = tid & 31, wid = tid >> 5;
    const int wm = wid & 3, wn = wid >> 2;
    const int mbase = wm * 32, kbase = wn * 64;

    const int iBlk = (NBLK - 1) - (int)blockIdx.y;   // heavy T-blocks first
    const int bh = blockIdx.x, b = bh >> 4, h = bh & 15;
    const float* base = qkv + (size_t)b * S_LEN * ROWSTRIDE + h * DIM;
    const float* gQ = base;
    const float* gK = base + NH * DIM;
    const float* gV = base + 2 * NH * DIM;
    const int t0 = iBlk * BLK;

    // Q tile (scaled by 2), split into smem
    {
        float4 q[8];
        ldg_tile(q, gQ + (size_t)t0 * ROWSTRIDE, tid);
        sts_split(sm, OFF_Q, q, 2.0f, tid);
    }

    // ================= pass 1: po = partial of tril(2Q K^T) K  (= 2*O2) =================
    float po[2][8][4];
    ZERO_PO(po);
    {
        float4 kv[8];
        ldg_tile(kv, gK, tid);                        // j = 0
        for (int j = 0; j <= iBlk; ++j) {
            __syncthreads();                          // sK free (prev gemm2 done)
            sts_split(sm, OFF_K, kv, 1.0f, tid);
            __syncthreads();

            float acc1[2][8][4];
            ZERO_PO(acc1);
            gemm_nT(sb + OFF_Q, sb + OFF_K, acc1, lane, mbase, kbase);   // 2Q K^T

            u32 pH[2][4][4], pL[2][4][4];
            mask_pack(acc1, pH, pL, lane, mbase, kbase, j == iBlk);

            if (j < iBlk)                             // prefetch next K under MMAs
                ldg_tile(kv, gK + (size_t)(j + 1) * BLK * ROWSTRIDE, tid);

            gemm2_reg(pH, pL, sb + OFF_K, po, lane, kbase);              // += S K
        }
    }

    // cross-warp reduce po (wn pairs) -> -O2 split tiles in sO2
    __syncthreads();
    if (wn == 1) {
#pragma unroll
        for (int mt = 0; mt < 2; ++mt)
#pragma unroll
            for (int nt = 0; nt < 8; ++nt)
#pragma unroll
                for (int rr = 0; rr < 2; ++rr) {
                    int rl = mt * 16 + (lane >> 2) + rr * 8;
                    int col = nt * 8 + ((lane & 3) << 1);
                    float2 v = make_float2(po[mt][nt][rr * 2], po[mt][nt][rr * 2 + 1]);
                    *reinterpret_cast<float2*>(sm + STG_OFF + wm * 8192 + rl * 256 + col * 4) = v;
                }
    }
    __syncthreads();
    if (wn == 0) {
#pragma unroll
        for (int mt = 0; mt < 2; ++mt)
#pragma unroll
            for (int nt = 0; nt < 8; ++nt)
#pragma unroll
                for (int rr = 0; rr < 2; ++rr) {
                    int rl = mt * 16 + (lane >> 2) + rr * 8;
                    int col = nt * 8 + ((lane & 3) << 1);
                    float2 p = *reinterpret_cast<float2*>(sm + STG_OFF + wm * 8192 + rl * 256 + col * 4);
                    float v0 = -0.5f * (po[mt][nt][rr * 2]     + p.x);
                    float v1 = -0.5f * (po[mt][nt][rr * 2 + 1] + p.y);
                    __nv_bfloat16 h0, l0, h1, l1;
                    split2(v0, h0, l0); split2(v1, h1, l1);
                    u32 o = off64(mbase + rl, col << 1);
                    __nv_bfloat162 pk;
                    pk.x = h0; pk.y = h1; *reinterpret_cast<__nv_bfloat162*>(sm + OFF_O2 + o)        = pk;
                    pk.x = l0; pk.y = l1; *reinterpret_cast<__nv_bfloat162*>(sm + OFF_O2 + HL64 + o) = pk;
                }
    }

    // ===== pass 2: po = partial of tril(2Q K^T + (-O2) K^T) V = (2A1 - A2) V =====
    ZERO_PO(po);
    {
        float4 kvK[8], kvV[8];
        ldg_tile(kvK, gK, tid);
        ldg_tile(kvV, gV, tid);
        for (int j = 0; j <= iBlk; ++j) {
            __syncthreads();                          // sK/sV free; sO2 ready (j=0)
            sts_split(sm, OFF_K, kvK, 1.0f, tid);
            sts_split(sm, OFF_V, kvV, 1.0f, tid);
            __syncthreads();

            float acc1[2][8][4];
            ZERO_PO(acc1);
            gemm_nT(sb + OFF_Q,  sb + OFF_K, acc1, lane, mbase, kbase);  // 2Q K^T
            gemm_nT(sb + OFF_O2, sb + OFF_K, acc1, lane, mbase, kbase);  // += (-O2) K^T

            u32 pH[2][4][4], pL[2][4][4];
            mask_pack(acc1, pH, pL, lane, mbase, kbase, j == iBlk);

            if (j < iBlk) {                           // prefetch next K,V under MMAs
                ldg_tile(kvK, gK + (size_t)(j + 1) * BLK * ROWSTRIDE, tid);
                ldg_tile(kvV, gV + (size_t)(j + 1) * BLK * ROWSTRIDE, tid);
            }

            gemm2_reg(pH, pL, sb + OFF_V, po, lane, kbase);              // += S V
        }
    }

    // cross-warp reduce po -> final out
    __syncthreads();
    if (wn == 1) {
#pragma unroll
        for (int mt = 0; mt < 2; ++mt)
#pragma unroll
            for (int nt = 0; nt < 8; ++nt)
#pragma unroll
                for (int rr = 0; rr < 2; ++rr) {
                    int rl = mt * 16 + (lane >> 2) + rr * 8;
                    int col = nt * 8 + ((lane & 3) << 1);
                    float2 v = make_float2(po[mt][nt][rr * 2], po[mt][nt][rr * 2 + 1]);
                    *reinterpret_cast<float2*>(sm + STG_OFF + wm * 8192 + rl * 256 + col * 4) = v;
                }
    }
    __syncthreads();
    if (wn == 0) {
#pragma unroll
        for (int mt = 0; mt < 2; ++mt)
#pragma unroll
            for (int nt = 0; nt < 8; ++nt)
#pragma unroll
                for (int rr = 0; rr < 2; ++rr) {
                    int rl = mt * 16 + (lane >> 2) + rr * 8;
                    int col = nt * 8 + ((lane & 3) << 1);
                    float2 p = *reinterpret_cast<float2*>(sm + STG_OFF + wm * 8192 + rl * 256 + col * 4);
                    float2 v = make_float2(po[mt][nt][rr * 2] + p.x,
                                           po[mt][nt][rr * 2 + 1] + p.y);
                    size_t off = (((size_t)b * S_LEN + t0 + mbase + rl) * NH + h) * DIM + col;
                    *reinterpret_cast<float2*>(out + off) = v;
                }
    }
}

extern "C" void kernel_launch(void* const* d_in, const int* in_sizes, int n_in,
                              void* d_out, int out_size) {
    const float* qkv = (const float*)d_in[0];
    float* out = (float*)d_out;
    cudaFuncSetAttribute(ttt_mma_kernel, cudaFuncAttributeMaxDynamicSharedMemorySize,
                         SMEM_TOTAL);
    dim3 grid(32 /*b*h*/, NBLK /*reversed T-blocks*/);
    ttt_mma_kernel<<<grid, 256, SMEM_TOTAL>>>(qkv, out);
}

// round 5
// speedup vs baseline: 2.8207x; 1.0880x over previous
#include <cuda_runtime.h>
#include <cuda_bf16.h>
#include <cstdint>

typedef uint32_t u32;

#define S_LEN 2048
#define NH 16
#define DIM 64
#define BLKM 64          // T rows per CTA
#define BLKS 128         // K/V rows per j-step
#define NMB 32           // S_LEN / BLKM
#define ROWSTRIDE 3072   // 3*NH*DIM floats between consecutive s rows

#define HLQ 8192         // one [64][64] bf16 half-tile
#define HLK 16384        // one [128][64] bf16 half-tile
// smem layout (each buffer = hi tile then lo tile, off64 swizzled)
#define OFF_Q   0
#define OFF_K   (OFF_Q + 2*HLQ)        // 16384
#define OFF_V   (OFF_K + 2*HLK)        // 49152
#define OFF_O2  (OFF_V + 2*HLK)        // 81920
#define SMEM_TOTAL (OFF_O2 + 2*HLQ)    // 98304 B
#define STG_OFF OFF_K                   // f32 staging for cross-warp reduce (16KB)

// ------------------------------------------------------------------ helpers
__device__ __forceinline__ u32 smem_u32(const void* p) {
    u32 a; asm("{ .reg .u64 t; cvta.to.shared.u64 t, %1; cvt.u32.u64 %0, t; }"
               : "=r"(a) : "l"(p));
    return a;
}
__device__ __forceinline__ u32 off64(int r, int cb) { return (u32)(r * 128 + (cb ^ ((r & 7) << 4))); }

__device__ __forceinline__ void ldsm4(u32 a, u32& r0, u32& r1, u32& r2, u32& r3) {
    asm volatile("ldmatrix.sync.aligned.m8n8.x4.shared.b16 {%0,%1,%2,%3}, [%4];"
        : "=r"(r0), "=r"(r1), "=r"(r2), "=r"(r3) : "r"(a));
}
__device__ __forceinline__ void ldsm4t(u32 a, u32& r0, u32& r1, u32& r2, u32& r3) {
    asm volatile("ldmatrix.sync.aligned.m8n8.x4.trans.shared.b16 {%0,%1,%2,%3}, [%4];"
        : "=r"(r0), "=r"(r1), "=r"(r2), "=r"(r3) : "r"(a));
}
__device__ __forceinline__ void mma_bf16(float* c, u32 a0, u32 a1, u32 a2, u32 a3,
                                         u32 b0, u32 b1) {
    asm volatile("mma.sync.aligned.m16n8k16.row.col.f32.bf16.bf16.f32 "
        "{%0,%1,%2,%3}, {%4,%5,%6,%7}, {%8,%9}, {%0,%1,%2,%3};"
        : "+f"(c[0]), "+f"(c[1]), "+f"(c[2]), "+f"(c[3])
        : "r"(a0), "r"(a1), "r"(a2), "r"(a3), "r"(b0), "r"(b1));
}
__device__ __forceinline__ void split2(float x, __nv_bfloat16& h, __nv_bfloat16& l) {
    h = __float2bfloat16(x);
    l = __float2bfloat16(x - __bfloat162float(h));
}
__device__ __forceinline__ void split_pack(float v0, float v1, u32& hp, u32& lp) {
    __nv_bfloat16 h0, l0, h1, l1;
    split2(v0, h0, l0); split2(v1, h1, l1);
    __nv_bfloat162 hh; hh.x = h0; hh.y = h1;
    __nv_bfloat162 ll; ll.x = l0; ll.y = l1;
    hp = *reinterpret_cast<u32*>(&hh);
    lp = *reinterpret_cast<u32*>(&ll);
}

// ---- load R x 64 fp32 gmem block -> split-bf16 hi/lo swizzled smem (128 thr) ----
template <int NIT, int HL>
__device__ __forceinline__ void load_split(char* sm, int base, const float* src,
                                           float scale, int tid) {
#pragma unroll
    for (int it = 0; it < NIT; ++it) {
        int f = tid + it * 128;
        int s = f >> 4, dq = (f & 15) << 2;
        float4 v = *reinterpret_cast<const float4*>(src + (size_t)s * ROWSTRIDE + dq);
        __nv_bfloat16 h0, l0, h1, l1, h2, l2, h3, l3;
        split2(v.x * scale, h0, l0); split2(v.y * scale, h1, l1);
        split2(v.z * scale, h2, l2); split2(v.w * scale, h3, l3);
        u32 o = off64(s, dq << 1);
        __nv_bfloat162 p;
        p.x = h0; p.y = h1; *reinterpret_cast<__nv_bfloat162*>(sm + base + o)          = p;
        p.x = h2; p.y = h3; *reinterpret_cast<__nv_bfloat162*>(sm + base + o + 4)      = p;
        p.x = l0; p.y = l1; *reinterpret_cast<__nv_bfloat162*>(sm + base + HL + o)     = p;
        p.x = l2; p.y = l3; *reinterpret_cast<__nv_bfloat162*>(sm + base + HL + o + 4) = p;
    }
}

// ---- GEMM1: acc[32x64 slice] += A[rows x 64] * (B[128x64])^T, 3-term split ----
template <int HLA, int HLB>
__device__ __forceinline__ void gemm_nT(u32 aHi, u32 bHi, float (&acc)[2][8][4],
                                        int lane, int mbase, int nbase) {
    const int arL = lane & 15, acL = (lane >> 4) << 4;
    const int brL = ((lane >> 4) << 3) + (lane & 7), bcL = ((lane >> 3) & 1) << 4;
#pragma unroll
    for (int kk = 0; kk < 4; ++kk) {
        const int kb = kk << 5;
        u32 aH[2][4], aL[2][4];
#pragma unroll
        for (int mt = 0; mt < 2; ++mt) {
            u32 ad = aHi + off64(mbase + mt * 16 + arL, kb + acL);
            ldsm4(ad,       aH[mt][0], aH[mt][1], aH[mt][2], aH[mt][3]);
            ldsm4(ad + HLA, aL[mt][0], aL[mt][1], aL[mt][2], aL[mt][3]);
        }
#pragma unroll
        for (int nt2 = 0; nt2 < 4; ++nt2) {
            u32 bd = bHi + off64(nbase + nt2 * 16 + brL, kb + bcL);
            u32 bh0, bh1, bh2, bh3, bl0, bl1, bl2, bl3;
            ldsm4(bd,       bh0, bh1, bh2, bh3);
            ldsm4(bd + HLB, bl0, bl1, bl2, bl3);
#pragma unroll
            for (int mt = 0; mt < 2; ++mt) {
                float* c0 = acc[mt][nt2 * 2];
                float* c1 = acc[mt][nt2 * 2 + 1];
                mma_bf16(c0, aH[mt][0], aH[mt][1], aH[mt][2], aH[mt][3], bh0, bh1);
                mma_bf16(c0, aH[mt][0], aH[mt][1], aH[mt][2], aH[mt][3], bl0, bl1);
                mma_bf16(c0, aL[mt][0], aL[mt][1], aL[mt][2], aL[mt][3], bh0, bh1);
                mma_bf16(c1, aH[mt][0], aH[mt][1], aH[mt][2], aH[mt][3], bh2, bh3);
                mma_bf16(c1, aH[mt][0], aH[mt][1], aH[mt][2], aH[mt][3], bl2, bl3);
                mma_bf16(c1, aL[mt][0], aL[mt][1], aL[mt][2], aL[mt][3], bh2, bh3);
            }
        }
    }
}

// ---- mask (absolute row/col) + in-register split into A-operand packs ----
__device__ __forceinline__ void mask_pack(float (&acc)[2][8][4],
                                          u32 (&pH)[2][4][4], u32 (&pL)[2][4][4],
                                          int lane, int rowAbs0, int colAbs0, bool diag) {
    if (diag) {
#pragma unroll
        for (int mt = 0; mt < 2; ++mt)
#pragma unroll
            for (int nt = 0; nt < 8; ++nt) {
                int col = colAbs0 + nt * 8 + ((lane & 3) << 1);
#pragma unroll
                for (int rr = 0; rr < 2; ++rr) {
                    int row = rowAbs0 + mt * 16 + (lane >> 2) + rr * 8;
                    if (col     > row) acc[mt][nt][rr * 2 + 0] = 0.0f;
                    if (col + 1 > row) acc[mt][nt][rr * 2 + 1] = 0.0f;
                }
            }
    }
#pragma unroll
    for (int mt = 0; mt < 2; ++mt)
#pragma unroll
        for (int kk = 0; kk < 4; ++kk) {
            split_pack(acc[mt][2*kk  ][0], acc[mt][2*kk  ][1], pH[mt][kk][0], pL[mt][kk][0]);
            split_pack(acc[mt][2*kk  ][2], acc[mt][2*kk  ][3], pH[mt][kk][1], pL[mt][kk][1]);
            split_pack(acc[mt][2*kk+1][0], acc[mt][2*kk+1][1], pH[mt][kk][2], pL[mt][kk][2]);
            split_pack(acc[mt][2*kk+1][2], acc[mt][2*kk+1][3], pH[mt][kk][3], pL[mt][kk][3]);
        }
}

// ---- GEMM2: po[32x64] += S_slice(regs) * B[k-slice x 64], B via ldmatrix.trans ----
__device__ __forceinline__ void gemm2_reg(const u32 (&pH)[2][4][4], const u32 (&pL)[2][4][4],
                                          u32 bHi, float (&po)[2][8][4],
                                          int lane, int kbase) {
    const int brL = (((lane >> 3) & 1) << 3) + (lane & 7), bcL = (lane >> 4) << 4;
#pragma unroll
    for (int kk = 0; kk < 4; ++kk) {
#pragma unroll
        for (int nt2 = 0; nt2 < 4; ++nt2) {
            u32 bd = bHi + off64(kbase + kk * 16 + brL, (nt2 << 5) + bcL);
            u32 bh0, bh1, bh2, bh3, bl0, bl1, bl2, bl3;
            ldsm4t(bd,       bh0, bh1, bh2, bh3);
            ldsm4t(bd + HLK, bl0, bl1, bl2, bl3);
#pragma unroll
            for (int mt = 0; mt < 2; ++mt) {
                float* c0 = po[mt][nt2 * 2];
                float* c1 = po[mt][nt2 * 2 + 1];
                mma_bf16(c0, pH[mt][kk][0], pH[mt][kk][1], pH[mt][kk][2], pH[mt][kk][3], bh0, bh1);
                mma_bf16(c0, pH[mt][kk][0], pH[mt][kk][1], pH[mt][kk][2], pH[mt][kk][3], bl0, bl1);
                mma_bf16(c0, pL[mt][kk][0], pL[mt][kk][1], pL[mt][kk][2], pL[mt][kk][3], bh0, bh1);
                mma_bf16(c1, pH[mt][kk][0], pH[mt][kk][1], pH[mt][kk][2], pH[mt][kk][3], bh2, bh3);
                mma_bf16(c1, pH[mt][kk][0], pH[mt][kk][1], pH[mt][kk][2], pH[mt][kk][3], bl2, bl3);
                mma_bf16(c1, pL[mt][kk][0], pL[mt][kk][1], pL[mt][kk][2], pL[mt][kk][3], bh2, bh3);
            }
        }
    }
}

#define ZERO_PO(po) \
    _Pragma("unroll") for (int mt = 0; mt < 2; ++mt) \
    _Pragma("unroll") for (int nt = 0; nt < 8; ++nt) \
    _Pragma("unroll") for (int e = 0; e < 4; ++e) (po)[mt][nt][e] = 0.0f;

__global__ void __launch_bounds__(128, 2)
ttt_mma_kernel(const float* __restrict__ qkv, float* __restrict__ out) {
    extern __shared__ char sm[];
    const u32 sb = smem_u32(sm);
    const int tid = threadIdx.x, lane = tid & 31, wid = tid >> 5;
    const int wm = wid & 1, wn = wid >> 1;
    const int mbase = wm * 32, kbase = wn * 64;

    const int mb = (NMB - 1) - (int)blockIdx.y;     // heavy T-blocks first
    const int bh = blockIdx.x, b = bh >> 4, h = bh & 15;
    const float* base = qkv + (size_t)b * S_LEN * ROWSTRIDE + h * DIM;
    const float* gQ = base;
    const float* gK = base + NH * DIM;
    const float* gV = base + 2 * NH * DIM;
    const int t0 = mb * BLKM;
    const int nK = (mb >> 1) + 1;                   // 128-row K blocks needed

    // Q tile (scaled by 2), split into smem
    load_split<8, HLQ>(sm, OFF_Q, gQ + (size_t)t0 * ROWSTRIDE, 2.0f, tid);

    // ================= pass 1: po = partial of tril(2Q K^T) K  (= 2*O2) =================
    float po[2][8][4];
    ZERO_PO(po);
    for (int j = 0; j < nK; ++j) {
        __syncthreads();                            // sK free (prev gemm2 done)
        load_split<16, HLK>(sm, OFF_K, gK + (size_t)j * BLKS * ROWSTRIDE, 1.0f, tid);
        __syncthreads();

        float acc1[2][8][4];
        ZERO_PO(acc1);
        gemm_nT<HLQ, HLK>(sb + OFF_Q, sb + OFF_K, acc1, lane, mbase, kbase);  // 2Q K^T

        u32 pH[2][4][4], pL[2][4][4];
        mask_pack(acc1, pH, pL, lane, t0 + mbase, j * BLKS + kbase, j == nK - 1);

        gemm2_reg(pH, pL, sb + OFF_K, po, lane, kbase);                       // += S K
    }

    // cross-warp reduce po (wn pairs) -> -O2 split tiles in sO2
    __syncthreads();
    if (wn == 1) {
#pragma unroll
        for (int mt = 0; mt < 2; ++mt)
#pragma unroll
            for (int nt = 0; nt < 8; ++nt)
#pragma unroll
                for (int rr = 0; rr < 2; ++rr) {
                    int rl = mt * 16 + (lane >> 2) + rr * 8;
                    int col = nt * 8 + ((lane & 3) << 1);
                    float2 v = make_float2(po[mt][nt][rr * 2], po[mt][nt][rr * 2 + 1]);
                    *reinterpret_cast<float2*>(sm + STG_OFF + wm * 8192 + rl * 256 + col * 4) = v;
                }
    }
    __syncthreads();
    if (wn == 0) {
#pragma unroll
        for (int mt = 0; mt < 2; ++mt)
#pragma unroll
            for (int nt = 0; nt < 8; ++nt)
#pragma unroll
                for (int rr = 0; rr < 2; ++rr) {
                    int rl = mt * 16 + (lane >> 2) + rr * 8;
                    int col = nt * 8 + ((lane & 3) << 1);
                    float2 p = *reinterpret_cast<float2*>(sm + STG_OFF + wm * 8192 + rl * 256 + col * 4);
                    float v0 = -0.5f * (po[mt][nt][rr * 2]     + p.x);
                    float v1 = -0.5f * (po[mt][nt][rr * 2 + 1] + p.y);
                    __nv_bfloat16 h0, l0, h1, l1;
                    split2(v0, h0, l0); split2(v1, h1, l1);
                    u32 o = off64(mbase + rl, col << 1);
                    __nv_bfloat162 pk;
                    pk.x = h0; pk.y = h1; *reinterpret_cast<__nv_bfloat162*>(sm + OFF_O2 + o)       = pk;
                    pk.x = l0; pk.y = l1; *reinterpret_cast<__nv_bfloat162*>(sm + OFF_O2 + HLQ + o) = pk;
                }
    }

    // ===== pass 2: po = partial of tril(2Q K^T + (-O2) K^T) V = (2A1 - A2) V =====
    ZERO_PO(po);
    for (int j = 0; j < nK; ++j) {
        __syncthreads();                            // sK/sV free; sO2/staging settled
        load_split<16, HLK>(sm, OFF_K, gK + (size_t)j * BLKS * ROWSTRIDE, 1.0f, tid);
        load_split<16, HLK>(sm, OFF_V, gV + (size_t)j * BLKS * ROWSTRIDE, 1.0f, tid);
        __syncthreads();

        float acc1[2][8][4];
        ZERO_PO(acc1);
        gemm_nT<HLQ, HLK>(sb + OFF_Q,  sb + OFF_K, acc1, lane, mbase, kbase);  // 2Q K^T
        gemm_nT<HLQ, HLK>(sb + OFF_O2, sb + OFF_K, acc1, lane, mbase, kbase);  // += (-O2) K^T

        u32 pH[2][4][4], pL[2][4][4];
        mask_pack(acc1, pH, pL, lane, t0 + mbase, j * BLKS + kbase, j == nK - 1);

        gemm2_reg(pH, pL, sb + OFF_V, po, lane, kbase);                        // += S V
    }

    // cross-warp reduce po -> final out
    __syncthreads();
    if (wn == 1) {
#pragma unroll
        for (int mt = 0; mt < 2; ++mt)
#pragma unroll
            for (int nt = 0; nt < 8; ++nt)
#pragma unroll
                for (int rr = 0; rr < 2; ++rr) {
                    int rl = mt * 16 + (lane >> 2) + rr * 8;
                    int col = nt * 8 + ((lane & 3) << 1);
                    float2 v = make_float2(po[mt][nt][rr * 2], po[mt][nt][rr * 2 + 1]);
                    *reinterpret_cast<float2*>(sm + STG_OFF + wm * 8192 + rl * 256 + col * 4) = v;
                }
    }
    __syncthreads();
    if (wn == 0) {
#pragma unroll
        for (int mt = 0; mt < 2; ++mt)
#pragma unroll
            for (int nt = 0; nt < 8; ++nt)
#pragma unroll
                for (int rr = 0; rr < 2; ++rr) {
                    int rl = mt * 16 + (lane >> 2) + rr * 8;
                    int col = nt * 8 + ((lane & 3) << 1);
                    float2 p = *reinterpret_cast<float2*>(sm + STG_OFF + wm * 8192 + rl * 256 + col * 4);
                    float2 v = make_float2(po[mt][nt][rr * 2] + p.x,
                                           po[mt][nt][rr * 2 + 1] + p.y);
                    size_t off = (((size_t)b * S_LEN + t0 + mbase + rl) * NH + h) * DIM + col;
                    *reinterpret_cast<float2*>(out + off) = v;
                }
    }
}

extern "C" void kernel_launch(void* const* d_in, const int* in_sizes, int n_in,
                              void* d_out, int out_size) {
    const float* qkv = (const float*)d_in[0];
    float* out = (float*)d_out;
    cudaFuncSetAttribute(ttt_mma_kernel, cudaFuncAttributeMaxDynamicSharedMemorySize,
                         SMEM_TOTAL);
    dim3 grid(32 /*b*h*/, NMB /*reversed T-blocks*/);
    ttt_mma_kernel<<<grid, 128, SMEM_TOTAL>>>(qkv, out);
}